// round 3
// baseline (speedup 1.0000x reference)
#include <cuda_runtime.h>
#include <cuda_bf16.h>
#include <cstdint>

#define NNODES 50000
#define FDIM   64
#define NEDGES 800000

// Scratch (static device allocation — allowed). 16B-aligned for v4 red.
__device__ __align__(16) float g_agg[(size_t)NNODES * FDIM];
__device__ float g_deg[NNODES];
__device__ int   g_idx_is_i32;

// ---------------------------------------------------------------------------
// Kernel 0: detect index dtype (int32 vs int64 payload).
// ---------------------------------------------------------------------------
__global__ void detect_kernel(const int* __restrict__ ei32) {
    unsigned v = 0;
    for (int k = threadIdx.x; k < 256; k += 32)
        v |= (unsigned)ei32[2 * k + 1];
#pragma unroll
    for (int off = 16; off > 0; off >>= 1)
        v |= __shfl_xor_sync(0xffffffffu, v, off);
    if (threadIdx.x == 0)
        g_idx_is_i32 = (v != 0u) ? 1 : 0;
}

// ---------------------------------------------------------------------------
// Kernel 1: zero scratch
// ---------------------------------------------------------------------------
__global__ void zero_kernel() {
    int i = blockIdx.x * blockDim.x + threadIdx.x;
    if (i < (NNODES * FDIM) / 4)
        ((float4*)g_agg)[i] = make_float4(0.f, 0.f, 0.f, 0.f);
    if (i < NNODES)
        g_deg[i] = 0.f;
}

// Vector reduction: one 16B red op instead of 4 scalar atomics (sm_90+)
__device__ __forceinline__ void red_add_v4(float* addr, float4 v) {
    asm volatile("red.global.add.v4.f32 [%0], {%1, %2, %3, %4};"
                 :: "l"(addr), "f"(v.x), "f"(v.y), "f"(v.z), "f"(v.w)
                 : "memory");
}

// ---------------------------------------------------------------------------
// Kernel 2: edge scatter (16 threads/edge, one float4 lane each)
// ---------------------------------------------------------------------------
__global__ void scatter_kernel(const float* __restrict__ x,
                               const void* __restrict__ ei_raw) {
    long long t = (long long)blockIdx.x * blockDim.x + threadIdx.x;
    int e = (int)(t >> 4);
    int j = (int)(t & 15);
    if (e >= NEDGES) return;

    int row, col;
    if (g_idx_is_i32) {
        const int* ei = (const int*)ei_raw;
        row = ei[e];
        col = ei[NEDGES + e];
    } else {
        const long long* ei = (const long long*)ei_raw;
        row = (int)ei[e];
        col = (int)ei[NEDGES + e];
    }
    if ((unsigned)row >= NNODES || (unsigned)col >= NNODES) return;

    float4 v = ((const float4*)(x + (size_t)col * FDIM))[j];
    red_add_v4(g_agg + (size_t)row * FDIM + j * 4, v);

    if (j == 0)
        atomicAdd(&g_deg[row], 1.0f);
}

// ---------------------------------------------------------------------------
// Packed f32x2 FMA helpers (Blackwell; only reachable via PTX)
// ---------------------------------------------------------------------------
__device__ __forceinline__ void fma2(unsigned long long& d,
                                     unsigned long long a,
                                     unsigned long long b) {
    asm("fma.rn.f32x2 %0, %1, %2, %0;" : "+l"(d) : "l"(a), "l"(b));
}
__device__ __forceinline__ unsigned long long pack2(float x, float y) {
    unsigned long long r;
    asm("mov.b64 %0, {%1, %2};" : "=l"(r) : "f"(x), "f"(y));
    return r;
}

// ---------------------------------------------------------------------------
// Kernel 3: fused mean + linear, register-tiled.
// 256 threads: thread = (node_l = tid>>3) in [0,32), (co = tid&7) -> 8 cols.
// Wt[k][o] transposed via conflict-free two-stage smem transpose.
// Inner loop: 1 LDS (broadcast a) + 1 pack + 2 LDS.128 (W pairs) + 4 FFMA2.
// ---------------------------------------------------------------------------
#define TILE_NODES 32
#define AS_STRIDE  68   // pad: float4-aligned, 4-bank node separation

__global__ void __launch_bounds__(256)
linear_kernel(const float* __restrict__ W,
              const float* __restrict__ b,
              float* __restrict__ out) {
    __shared__ __align__(16) float Wt[64 * 64];     // Wt[k*64 + o] = W[o][k]
    __shared__ __align__(16) float pool[64 * 65];   // stage W, then 'as' tile

    int tid    = threadIdx.x;
    int node_l = tid >> 3;
    int co     = tid & 7;

    // --- Stage 1: coalesced global read of W into padded pool[o*65+k] ---
    for (int i = tid; i < 64 * 64; i += 256) {
        int o = i >> 6, k = i & 63;
        pool[o * 65 + k] = W[i];    // STS banks (o+k)%32, k varies -> CF
    }
    __syncthreads();
    // --- Stage 2: transpose pool -> Wt (both sides conflict-free) ---
    for (int j = tid; j < 64 * 64; j += 256) {
        int k = j >> 6, o = j & 63;
        Wt[k * 64 + o] = pool[o * 65 + k];  // LDS (o+k)%32, STS o%32, o varies
    }

    // bias pairs for this thread's 8 columns
    ulonglong2 bA = *(const ulonglong2*)(b + co * 8);
    ulonglong2 bB = *(const ulonglong2*)(b + co * 8 + 4);
    __syncthreads();   // pool now free for reuse as activation tile

    int ntiles = (NNODES + TILE_NODES - 1) / TILE_NODES;
    for (int tile = blockIdx.x; tile < ntiles; tile += gridDim.x) {
        int base = tile * TILE_NODES;

        // --- stage 'as' tile: 512 float4 loads, scaled by 1/deg ---
#pragma unroll
        for (int s = 0; s < 2; s++) {
            int idx = tid + s * 256;          // float4 index in [0,512)
            int nl  = idx >> 4;
            int j   = idx & 15;
            int gn  = base + nl;
            int cn  = gn < NNODES ? gn : (NNODES - 1);
            float inv = (gn < NNODES) ? (1.0f / (g_deg[cn] + 1e-6f)) : 0.0f;
            float4 v = ((const float4*)(g_agg + (size_t)cn * FDIM))[j];
            v.x *= inv; v.y *= inv; v.z *= inv; v.w *= inv;
            *(float4*)&pool[nl * AS_STRIDE + j * 4] = v;
        }
        __syncthreads();

        // --- compute 8 outputs per thread ---
        unsigned long long acc0 = bA.x, acc1 = bA.y, acc2 = bB.x, acc3 = bB.y;
        int nbase = node_l * AS_STRIDE;
#pragma unroll
        for (int k = 0; k < 64; k++) {
            float a = pool[nbase + k];
            unsigned long long aa = pack2(a, a);
            const ulonglong2* wp = (const ulonglong2*)(Wt + (k << 6) + (co << 3));
            ulonglong2 wA = wp[0];
            ulonglong2 wB = wp[1];
            fma2(acc0, aa, wA.x);
            fma2(acc1, aa, wA.y);
            fma2(acc2, aa, wB.x);
            fma2(acc3, aa, wB.y);
        }

        int gnode = base + node_l;
        if (gnode < NNODES) {
            ulonglong2* op = (ulonglong2*)(out + (size_t)gnode * FDIM + co * 8);
            ulonglong2 r0; r0.x = acc0; r0.y = acc1;
            ulonglong2 r1; r1.x = acc2; r1.y = acc3;
            op[0] = r0;
            op[1] = r1;
        }
        __syncthreads();   // pool reused next tile
    }
}

// ---------------------------------------------------------------------------
// Launch
// ---------------------------------------------------------------------------
extern "C" void kernel_launch(void* const* d_in, const int* in_sizes, int n_in,
                              void* d_out, int out_size) {
    const float* x  = (const float*)d_in[0];
    const void*  ei = d_in[1];
    const float* W  = (const float*)d_in[2];
    const float* b  = (const float*)d_in[3];
    float*       out = (float*)d_out;

    detect_kernel<<<1, 32>>>((const int*)ei);

    {
        int n = (NNODES * FDIM) / 4;
        zero_kernel<<<(n + 255) / 256, 256>>>();
    }
    {
        long long work = (long long)NEDGES * 16;
        scatter_kernel<<<(int)((work + 255) / 256), 256>>>(x, ei);
    }
    {
        linear_kernel<<<1024, 256>>>(W, b, out);
    }
}

// round 5
// speedup vs baseline: 1.5293x; 1.5293x over previous
#include <cuda_runtime.h>
#include <cuda_bf16.h>
#include <cstdint>

#define NNODES 50000
#define FDIM   64
#define NEDGES 800000

// Scratch (static device allocation — allowed). 16B-aligned for v4 red.
__device__ __align__(16) float g_agg[(size_t)NNODES * FDIM];
__device__ float g_deg[NNODES];
__device__ int   g_idx_is_i32;

// ---------------------------------------------------------------------------
// Kernel 0: detect index dtype (int32 vs int64 payload).
// ---------------------------------------------------------------------------
__global__ void detect_kernel(const int* __restrict__ ei32) {
    unsigned v = 0;
    for (int k = threadIdx.x; k < 256; k += 32)
        v |= (unsigned)ei32[2 * k + 1];
#pragma unroll
    for (int off = 16; off > 0; off >>= 1)
        v |= __shfl_xor_sync(0xffffffffu, v, off);
    if (threadIdx.x == 0)
        g_idx_is_i32 = (v != 0u) ? 1 : 0;
}

// ---------------------------------------------------------------------------
// Kernel 1: zero scratch
// ---------------------------------------------------------------------------
__global__ void zero_kernel() {
    int i = blockIdx.x * blockDim.x + threadIdx.x;
    if (i < (NNODES * FDIM) / 4)
        ((float4*)g_agg)[i] = make_float4(0.f, 0.f, 0.f, 0.f);
    if (i < NNODES)
        g_deg[i] = 0.f;
}

// Vector reduction: one 16B red op instead of 4 scalar atomics (sm_90+)
__device__ __forceinline__ void red_add_v4(float* addr, float4 v) {
    asm volatile("red.global.add.v4.f32 [%0], {%1, %2, %3, %4};"
                 :: "l"(addr), "f"(v.x), "f"(v.y), "f"(v.z), "f"(v.w)
                 : "memory");
}

// ---------------------------------------------------------------------------
// Kernel 2: edge scatter (16 threads/edge, one float4 lane each)
// ---------------------------------------------------------------------------
__global__ void scatter_kernel(const float* __restrict__ x,
                               const void* __restrict__ ei_raw) {
    long long t = (long long)blockIdx.x * blockDim.x + threadIdx.x;
    int e = (int)(t >> 4);
    int j = (int)(t & 15);
    if (e >= NEDGES) return;

    int row, col;
    if (g_idx_is_i32) {
        const int* ei = (const int*)ei_raw;
        row = ei[e];
        col = ei[NEDGES + e];
    } else {
        const long long* ei = (const long long*)ei_raw;
        row = (int)ei[e];
        col = (int)ei[NEDGES + e];
    }
    if ((unsigned)row >= NNODES || (unsigned)col >= NNODES) return;

    float4 v = ((const float4*)(x + (size_t)col * FDIM))[j];
    red_add_v4(g_agg + (size_t)row * FDIM + j * 4, v);

    if (j == 0)
        atomicAdd(&g_deg[row], 1.0f);
}

// ---------------------------------------------------------------------------
// Packed f32x2 helpers (Blackwell; only reachable via PTX)
// ---------------------------------------------------------------------------
__device__ __forceinline__ void fma2(unsigned long long& d,
                                     unsigned long long a,
                                     unsigned long long b) {
    asm("fma.rn.f32x2 %0, %1, %2, %0;" : "+l"(d) : "l"(a), "l"(b));
}
__device__ __forceinline__ unsigned long long pack2(float x, float y) {
    unsigned long long r;
    asm("mov.b64 %0, {%1, %2};" : "=l"(r) : "f"(x), "f"(y));
    return r;
}

// ---------------------------------------------------------------------------
// Kernel 3: fused mean + linear. 8 nodes x 8 cols per thread.
// blockDim=128: thread = (ng = tid>>3 in [0,16), co = tid&7).
// Tile = 128 nodes. Per 4-k: 8 LDS.128 (a) + 8 LDS.128 (W) feed 128 FFMA2.
// ---------------------------------------------------------------------------
#define TN    128   // nodes per tile
#define S_AS  68    // as[node][k] row stride (floats, 16B-aligned)

__global__ void __launch_bounds__(128, 3)
linear_kernel(const float* __restrict__ W,
              const float* __restrict__ b,
              float* __restrict__ out) {
    __shared__ __align__(16) float Wt[64 * 64];      // Wt[k*64 + o] = W[o][k]
    __shared__ __align__(16) float as[TN * S_AS];    // also W staging (needs 64*65 <= TN*S_AS)

    int tid = threadIdx.x;
    int ng  = tid >> 3;   // node group 0..15
    int co  = tid & 7;    // col group: columns co*8 .. co*8+7

    // --- W transpose, two-stage conflict-free (as[] used as staging) ---
    for (int i = tid; i < 64 * 64; i += 128) {
        int o = i >> 6, k = i & 63;
        as[o * 65 + k] = W[i];
    }
    __syncthreads();
    for (int j = tid; j < 64 * 64; j += 128) {
        int k = j >> 6, o = j & 63;
        Wt[k * 64 + o] = as[o * 65 + k];
    }
    ulonglong2 bA = *(const ulonglong2*)(b + co * 8);
    ulonglong2 bB = *(const ulonglong2*)(b + co * 8 + 4);
    __syncthreads();   // as[] now free

    for (int tile = blockIdx.x; tile * TN < NNODES; tile += gridDim.x) {
        int base = tile * TN;

        // --- stage activation tile, fused 1/deg scale (coalesced gmem) ---
#pragma unroll
        for (int it = 0; it < 16; it++) {
            int flat = it * 128 + tid;
            int nl = flat >> 4;      // local node
            int j  = flat & 15;      // float4 index
            int gn = base + nl;
            int cn = gn < NNODES ? gn : (NNODES - 1);
            float inv = (gn < NNODES) ? (1.0f / (g_deg[cn] + 1e-6f)) : 0.0f;
            float4 v = ((const float4*)(g_agg + (size_t)cn * FDIM))[j];
            v.x *= inv; v.y *= inv; v.z *= inv; v.w *= inv;
            *(float4*)&as[nl * S_AS + j * 4] = v;
        }
        __syncthreads();

        // --- compute: 8 nodes x 8 cols, f32x2 over column pairs ---
        unsigned long long acc[8][4];
#pragma unroll
        for (int m = 0; m < 8; m++) {
            acc[m][0] = bA.x; acc[m][1] = bA.y;
            acc[m][2] = bB.x; acc[m][3] = bB.y;
        }

        const float* arow = as + (ng * 8) * S_AS;
#pragma unroll 2
        for (int k4 = 0; k4 < 64; k4 += 4) {
            float4 av[8];
#pragma unroll
            for (int m = 0; m < 8; m++)
                av[m] = *(const float4*)(arow + m * S_AS + k4);
#pragma unroll
            for (int kk = 0; kk < 4; kk++) {
                const ulonglong2* wp =
                    (const ulonglong2*)(Wt + ((k4 + kk) << 6) + (co << 3));
                ulonglong2 wA = wp[0];
                ulonglong2 wB = wp[1];
#pragma unroll
                for (int m = 0; m < 8; m++) {
                    float a = (kk == 0) ? av[m].x :
                              (kk == 1) ? av[m].y :
                              (kk == 2) ? av[m].z : av[m].w;
                    unsigned long long aa = pack2(a, a);
                    fma2(acc[m][0], aa, wA.x);
                    fma2(acc[m][1], aa, wA.y);
                    fma2(acc[m][2], aa, wB.x);
                    fma2(acc[m][3], aa, wB.y);
                }
            }
        }

        // --- store 8 nodes x 8 cols (two 16B stores per node) ---
        int gn0 = base + ng * 8;
#pragma unroll
        for (int m = 0; m < 8; m++) {
            int node = gn0 + m;
            if (node < NNODES) {
                ulonglong2 r0, r1;
                r0.x = acc[m][0]; r0.y = acc[m][1];
                r1.x = acc[m][2]; r1.y = acc[m][3];
                ulonglong2* op = (ulonglong2*)(out + (size_t)node * FDIM + co * 8);
                op[0] = r0;
                op[1] = r1;
            }
        }
        __syncthreads();
    }
}

// ---------------------------------------------------------------------------
// Launch
// ---------------------------------------------------------------------------
extern "C" void kernel_launch(void* const* d_in, const int* in_sizes, int n_in,
                              void* d_out, int out_size) {
    const float* x  = (const float*)d_in[0];
    const void*  ei = d_in[1];
    const float* W  = (const float*)d_in[2];
    const float* b  = (const float*)d_in[3];
    float*       out = (float*)d_out;

    detect_kernel<<<1, 32>>>((const int*)ei);

    {
        int n = (NNODES * FDIM) / 4;
        zero_kernel<<<(n + 255) / 256, 256>>>();
    }
    {
        long long work = (long long)NEDGES * 16;
        scatter_kernel<<<(int)((work + 255) / 256), 256>>>(x, ei);
    }
    {
        int tiles = (NNODES + TN - 1) / TN;   // 391
        linear_kernel<<<tiles, 128>>>(W, b, out);
    }
}

// round 6
// speedup vs baseline: 1.6423x; 1.0739x over previous
#include <cuda_runtime.h>
#include <cuda_bf16.h>
#include <cstdint>

#define NNODES 50000
#define FDIM   64
#define NEDGES 800000
#define NBLK   ((NNODES + 255) / 256)   // 196 scan blocks

// ---- static scratch (allowed) ----
__device__ __align__(16) float g_xw[(size_t)NNODES * FDIM];  // x @ W^T
__device__ int g_cnt[NNODES];        // degree histogram
__device__ int g_off[NNODES];        // CSR row offsets
__device__ int g_cur[NNODES];        // scatter cursors
__device__ int g_bsum[256];          // per-block sums  (NBLK used)
__device__ int g_boff[256];          // per-block exclusive offsets
__device__ int g_scol[NEDGES];       // cols sorted by row
__device__ int g_idx_is_i32;

// ---------------------------------------------------------------------------
// index helpers (harness delivers int64 edge_index as int32 payload; detect)
// ---------------------------------------------------------------------------
__global__ void detect_kernel(const int* __restrict__ ei32) {
    unsigned v = 0;
    for (int k = threadIdx.x; k < 256; k += 32)
        v |= (unsigned)ei32[2 * k + 1];
#pragma unroll
    for (int off = 16; off > 0; off >>= 1)
        v |= __shfl_xor_sync(0xffffffffu, v, off);
    if (threadIdx.x == 0)
        g_idx_is_i32 = (v != 0u) ? 1 : 0;
}

__device__ __forceinline__ int load_idx(const void* ei, int pos) {
    if (g_idx_is_i32) return ((const int*)ei)[pos];
    return (int)((const long long*)ei)[pos];
}

// ---------------------------------------------------------------------------
// CSR build: zero counters -> histogram -> 3-stage scan -> col scatter
// ---------------------------------------------------------------------------
__global__ void zero_cnt_kernel() {
    int i = blockIdx.x * blockDim.x + threadIdx.x;
    if (i < NNODES) g_cnt[i] = 0;
}

__global__ void hist_kernel(const void* __restrict__ ei) {
    int e = blockIdx.x * blockDim.x + threadIdx.x;
    if (e >= NEDGES) return;
    int row = load_idx(ei, e);
    if ((unsigned)row >= NNODES) return;
    atomicAdd(&g_cnt[row], 1);
}

__global__ void scan1_kernel() {   // per-block sums of g_cnt
    __shared__ int s[256];
    int i = blockIdx.x * 256 + threadIdx.x;
    s[threadIdx.x] = (i < NNODES) ? g_cnt[i] : 0;
    __syncthreads();
    for (int st = 128; st > 0; st >>= 1) {
        if (threadIdx.x < st) s[threadIdx.x] += s[threadIdx.x + st];
        __syncthreads();
    }
    if (threadIdx.x == 0) g_bsum[blockIdx.x] = s[0];
}

__global__ void scan2_kernel() {   // exclusive scan of block sums (1 block)
    __shared__ int s[256];
    int t = threadIdx.x;
    int v = (t < NBLK) ? g_bsum[t] : 0;
    s[t] = v;
    __syncthreads();
    for (int st = 1; st < 256; st <<= 1) {
        int a = (t >= st) ? s[t - st] : 0;
        __syncthreads();
        s[t] += a;
        __syncthreads();
    }
    g_boff[t] = s[t] - v;   // exclusive
}

__global__ void scan3_kernel() {   // final offsets + cursors
    __shared__ int s[256];
    int t = threadIdx.x;
    int i = blockIdx.x * 256 + t;
    int v = (i < NNODES) ? g_cnt[i] : 0;
    s[t] = v;
    __syncthreads();
    for (int st = 1; st < 256; st <<= 1) {
        int a = (t >= st) ? s[t - st] : 0;
        __syncthreads();
        s[t] += a;
        __syncthreads();
    }
    if (i < NNODES) {
        int off = g_boff[blockIdx.x] + s[t] - v;
        g_off[i] = off;
        g_cur[i] = off;
    }
}

__global__ void scatter_idx_kernel(const void* __restrict__ ei) {
    int e = blockIdx.x * blockDim.x + threadIdx.x;
    if (e >= NEDGES) return;
    int row = load_idx(ei, e);
    if ((unsigned)row >= NNODES) return;
    int col = load_idx(ei, NEDGES + e);
    if ((unsigned)col >= NNODES) col = 0;   // defensive
    int pos = atomicAdd(&g_cur[row], 1);
    g_scol[pos] = col;
}

// ---------------------------------------------------------------------------
// Packed f32x2 helpers
// ---------------------------------------------------------------------------
__device__ __forceinline__ void fma2(unsigned long long& d,
                                     unsigned long long a,
                                     unsigned long long b) {
    asm("fma.rn.f32x2 %0, %1, %2, %0;" : "+l"(d) : "l"(a), "l"(b));
}
__device__ __forceinline__ unsigned long long pack2(float x, float y) {
    unsigned long long r;
    asm("mov.b64 %0, {%1, %2};" : "=l"(r) : "f"(x), "f"(y));
    return r;
}

// ---------------------------------------------------------------------------
// GEMM: xw = x @ W^T.  4 nodes x 8 cols per thread, 256 threads, TN=128.
// ---------------------------------------------------------------------------
#define GTN  128
#define S_XS 68

__global__ void __launch_bounds__(256, 2)
gemm_kernel(const float* __restrict__ x, const float* __restrict__ W) {
    __shared__ __align__(16) float Wt[64 * 64];       // Wt[k*64+o]
    __shared__ __align__(16) float xs[GTN * S_XS];    // also W staging (64*65 fits)

    int tid = threadIdx.x;
    int ng  = tid >> 3;   // 0..31, nodes ng*4..+4
    int co  = tid & 7;    // cols co*8..+8

    // W transpose, two-stage conflict-free
    for (int i = tid; i < 64 * 64; i += 256) {
        int o = i >> 6, k = i & 63;
        xs[o * 65 + k] = W[i];
    }
    __syncthreads();
    for (int j = tid; j < 64 * 64; j += 256) {
        int k = j >> 6, o = j & 63;
        Wt[k * 64 + o] = xs[o * 65 + k];
    }
    __syncthreads();   // xs free

    int ntiles = (NNODES + GTN - 1) / GTN;
    for (int tile = blockIdx.x; tile < ntiles; tile += gridDim.x) {
        int base = tile * GTN;

        // stage x tile (coalesced)
#pragma unroll
        for (int it = 0; it < 8; it++) {
            int flat = it * 256 + tid;      // [0, 2048)
            int nl = flat >> 4;
            int j  = flat & 15;
            int gn = base + nl;
            int cn = gn < NNODES ? gn : (NNODES - 1);
            *(float4*)&xs[nl * S_XS + j * 4] =
                ((const float4*)(x + (size_t)cn * FDIM))[j];
        }
        __syncthreads();

        unsigned long long acc[4][4];
#pragma unroll
        for (int m = 0; m < 4; m++)
#pragma unroll
            for (int q = 0; q < 4; q++) acc[m][q] = 0ull;

        const float* arow = xs + (ng * 4) * S_XS;
#pragma unroll 2
        for (int k4 = 0; k4 < 64; k4 += 4) {
            float4 av[4];
#pragma unroll
            for (int m = 0; m < 4; m++)
                av[m] = *(const float4*)(arow + m * S_XS + k4);
#pragma unroll
            for (int kk = 0; kk < 4; kk++) {
                const ulonglong2* wp =
                    (const ulonglong2*)(Wt + ((k4 + kk) << 6) + (co << 3));
                ulonglong2 wA = wp[0];
                ulonglong2 wB = wp[1];
#pragma unroll
                for (int m = 0; m < 4; m++) {
                    float a = (kk == 0) ? av[m].x :
                              (kk == 1) ? av[m].y :
                              (kk == 2) ? av[m].z : av[m].w;
                    unsigned long long aa = pack2(a, a);
                    fma2(acc[m][0], aa, wA.x);
                    fma2(acc[m][1], aa, wA.y);
                    fma2(acc[m][2], aa, wB.x);
                    fma2(acc[m][3], aa, wB.y);
                }
            }
        }

        int gn0 = base + ng * 4;
#pragma unroll
        for (int m = 0; m < 4; m++) {
            int node = gn0 + m;
            if (node < NNODES) {
                ulonglong2 r0, r1;
                r0.x = acc[m][0]; r0.y = acc[m][1];
                r1.x = acc[m][2]; r1.y = acc[m][3];
                ulonglong2* op = (ulonglong2*)(g_xw + (size_t)node * FDIM + co * 8);
                op[0] = r0;
                op[1] = r1;
            }
        }
        __syncthreads();
    }
}

// ---------------------------------------------------------------------------
// Accumulate: out[row] = mean_{e in row} xw[col_e] + b.
// 16 lanes per row (one float4 each); 16 rows per 256-thread block.
// ---------------------------------------------------------------------------
__global__ void __launch_bounds__(256)
accum_kernel(const float* __restrict__ b, float* __restrict__ out) {
    int tid = threadIdx.x;
    int row = blockIdx.x * 16 + (tid >> 4);
    int j   = tid & 15;
    if (row >= NNODES) return;

    int start = g_off[row];
    int deg   = g_cnt[row];

    float4 v = make_float4(0.f, 0.f, 0.f, 0.f);
    for (int e = 0; e < deg; e++) {
        int col = g_scol[start + e];
        float4 xv = ((const float4*)(g_xw + (size_t)col * FDIM))[j];
        v.x += xv.x; v.y += xv.y; v.z += xv.z; v.w += xv.w;
    }

    float inv = 1.0f / ((float)deg + 1e-6f);
    float4 bb = ((const float4*)b)[j];
    float4 o;
    o.x = v.x * inv + bb.x;
    o.y = v.y * inv + bb.y;
    o.z = v.z * inv + bb.z;
    o.w = v.w * inv + bb.w;
    ((float4*)(out + (size_t)row * FDIM))[j] = o;
}

// ---------------------------------------------------------------------------
// Launch
// ---------------------------------------------------------------------------
extern "C" void kernel_launch(void* const* d_in, const int* in_sizes, int n_in,
                              void* d_out, int out_size) {
    const float* x  = (const float*)d_in[0];
    const void*  ei = d_in[1];
    const float* W  = (const float*)d_in[2];
    const float* b  = (const float*)d_in[3];
    float*       out = (float*)d_out;

    detect_kernel<<<1, 32>>>((const int*)ei);
    zero_cnt_kernel<<<NBLK, 256>>>();
    hist_kernel<<<(NEDGES + 255) / 256, 256>>>(ei);
    scan1_kernel<<<NBLK, 256>>>();
    scan2_kernel<<<1, 256>>>();
    scan3_kernel<<<NBLK, 256>>>();
    scatter_idx_kernel<<<(NEDGES + 255) / 256, 256>>>(ei);
    gemm_kernel<<<296, 256>>>(x, W);
    accum_kernel<<<(NNODES + 15) / 16, 256>>>(b, out);
}